// round 5
// baseline (speedup 1.0000x reference)
#include <cuda_runtime.h>
#include <math.h>

#define NH      8
#define LSEQ    512
#define DRES    384
#define DPAIR   128
#define DS      16
#define TJ      64
#define ROWF    132
#define NROW    1024
#define NFEAT   1280
#define NPROJ   672

#define SCALE_SCALAR 0.25f
#define SCALE_POINT  0.2357022603955158f   /* 18^-0.5 */
#define SCALE_TOTAL  0.5773502691896258f   /* 3^-0.5  */

// ---------------- scratch (device globals; no allocation) ----------------
__device__ float g_qs[2*NH*LSEQ*DS];
__device__ float g_ks[2*NH*LSEQ*DS];
__device__ float g_vs[2*NH*LSEQ*DS];
__device__ float g_qp[2*NH*LSEQ*12];
__device__ float g_kp[2*NH*LSEQ*12];
__device__ float g_vp[2*NH*LSEQ*12];
__device__ float g_praw[NROW*288];
__device__ float g_feat[(size_t)NROW*NFEAT];

// ---------------- kernel 1: projection GEMM  C[1024][672] = X @ [W...] ---
__global__ void __launch_bounds__(256) proj_gemm(
    const float* __restrict__ X,
    const float* __restrict__ Wqs, const float* __restrict__ Wks,
    const float* __restrict__ Wvs, const float* __restrict__ Wqp,
    const float* __restrict__ Wkp, const float* __restrict__ Wvp)
{
    __shared__ float As[8*65];
    __shared__ float Bs[8*64];
    int tid = threadIdx.x;
    int tx = tid & 15, ty = tid >> 4;
    int row0 = blockIdx.y * 64;
    int col0 = blockIdx.x * 64;
    float acc[4][4];
    #pragma unroll
    for (int i=0;i<4;i++)
        #pragma unroll
        for (int j=0;j<4;j++) acc[i][j]=0.f;

    for (int k0 = 0; k0 < DRES; k0 += 8) {
        #pragma unroll
        for (int s = 0; s < 2; s++) {
            int li = tid + s*256;
            int r = li >> 3, c = li & 7;
            As[c*65 + r] = X[(size_t)(row0 + r)*DRES + k0 + c];
        }
        #pragma unroll
        for (int s = 0; s < 2; s++) {
            int li = tid + s*256;
            int kr = li >> 6, c = li & 63;
            int col = col0 + c;
            float v = 0.f;
            if (col < NPROJ) {
                const float* wp; int segw, cl;
                if (col < 384) {
                    int sg = col >> 7;
                    wp = (sg==0) ? Wqs : ((sg==1) ? Wks : Wvs);
                    segw = 128; cl = col & 127;
                } else {
                    int c2 = col - 384; int sg = c2/96;
                    wp = (sg==0) ? Wqp : ((sg==1) ? Wkp : Wvp);
                    segw = 96; cl = c2 - sg*96;
                }
                v = wp[(size_t)(k0+kr)*segw + cl];
            }
            Bs[kr*64 + c] = v;
        }
        __syncthreads();
        #pragma unroll
        for (int kk = 0; kk < 8; kk++) {
            float a[4], bb[4];
            #pragma unroll
            for (int i=0;i<4;i++) a[i]  = As[kk*65 + ty*4 + i];
            #pragma unroll
            for (int j=0;j<4;j++) bb[j] = Bs[kk*64 + tx*4 + j];
            #pragma unroll
            for (int i=0;i<4;i++)
                #pragma unroll
                for (int j=0;j<4;j++) acc[i][j] += a[i]*bb[j];
        }
        __syncthreads();
    }
    #pragma unroll
    for (int i=0;i<4;i++) {
        int row = row0 + ty*4 + i;
        int b = row >> 9, l = row & 511;
        #pragma unroll
        for (int j=0;j<4;j++) {
            int col = col0 + tx*4 + j;
            if (col >= NPROJ) continue;
            float v = acc[i][j];
            if (col < 384) {
                int sg = col >> 7;
                int n = (col & 127) >> 4, d = col & 15;
                float* dst = (sg==0) ? g_qs : ((sg==1) ? g_ks : g_vs);
                dst[(((b*NH)+n)*LSEQ + l)*DS + d] = v;
            } else {
                g_praw[row*288 + (col-384)] = v;
            }
        }
    }
}

// ---------------- kernel 2: euclid transform of projected points ---------
__global__ void point_transform(const float* __restrict__ R, const float* __restrict__ T)
{
    int row = blockIdx.x;
    int b = row >> 9, l = row & 511;
    int t = threadIdx.x;
    if (t >= 96) return;
    int tensor = t / 32, idx = t % 32;
    int n = idx >> 2, p = idx & 3;
    const float* xr = &g_praw[row*288 + tensor*96 + n*12 + p*3];
    const float* rr = &R[row*9];
    const float* tt = &T[row*3];
    float x0 = xr[0], x1 = xr[1], x2 = xr[2];
    float* dst = ((tensor==0) ? g_qp : ((tensor==1) ? g_kp : g_vp))
               + (((b*NH)+n)*LSEQ + l)*12 + p*3;
    #pragma unroll
    for (int c = 0; c < 3; c++)
        dst[c] = x0*rr[0*3+c] + x1*rr[1*3+c] + x2*rr[2*3+c] + tt[c];
}

// ---------------- kernel 3: fused IPA attention (single e read) ----------
// smem float offsets
#define OFF_E      0
#define OFF_WPB    8448
#define OFF_LOGIT  9472
#define OFF_PROB   10000
#define OFF_PART   10528
#define OFF_QS     12832
#define OFF_QP     12960
#define OFF_GAMMA  13056
#define OFF_ALPHA  13064
#define OFF_DENOM  13072
#define OFF_OS     13080
#define OFF_OP     13208
#define SMEM_FLOATS 13304

__global__ void __launch_bounds__(256) ipa_attn(
    const float* __restrict__ E, const float* __restrict__ R,
    const float* __restrict__ T, const float* __restrict__ Wpb,
    const float* __restrict__ gamma)
{
    extern __shared__ float sm[];
    float* e_s     = sm + OFF_E;
    float* Wpb_s   = sm + OFF_WPB;
    float* logit_s = sm + OFF_LOGIT;
    float* prob_s  = sm + OFF_PROB;
    float* part_s  = sm + OFF_PART;
    float* qs_s    = sm + OFF_QS;
    float* qp_s    = sm + OFF_QP;
    float* gamma_s = sm + OFF_GAMMA;
    float* alpha_s = sm + OFF_ALPHA;
    float* denom_s = sm + OFF_DENOM;
    float* os_s    = sm + OFF_OS;
    float* op_s    = sm + OFF_OP;

    int row = blockIdx.x;
    int b = row >> 9, i = row & 511;
    int tid = threadIdx.x;
    int warp = tid >> 5, lane = tid & 31;

    for (int k = tid; k < DPAIR*NH; k += 256) Wpb_s[k] = Wpb[k];
    if (tid < 128) { int n = tid >> 4, d = tid & 15;
        qs_s[tid] = g_qs[((b*NH+n)*LSEQ + i)*DS + d]; }
    if (tid < 96)  { int n = tid/12, pc = tid - n*12;
        qp_s[tid] = g_qp[((b*NH+n)*LSEQ + i)*12 + pc]; }
    if (tid < 8) gamma_s[tid] = gamma[tid];
    __syncthreads();

    float m_run = -1e30f, denom = 0.f, acc_sp = 0.f;
    float acc_e[NH][4];
    #pragma unroll
    for (int n=0;n<NH;n++)
        #pragma unroll
        for (int c=0;c<4;c++) acc_e[n][c] = 0.f;

    const float* Ebi = E + (size_t)row * LSEQ * DPAIR;

    for (int jt = 0; jt < LSEQ/TJ; jt++) {
        int j0 = jt * TJ;

        // --- load e tile (contiguous 32KB) -> padded smem rows ---
        const float4* esrc = (const float4*)(Ebi + (size_t)j0*DPAIR);
        #pragma unroll
        for (int it = 0; it < 8; it++) {
            int g = it*256 + tid;                  // float4 index
            float4 v = esrc[g];
            int j = g >> 5, d = (g & 31) * 4;
            *(float4*)(e_s + j*ROWF + d) = v;
        }
        __syncthreads();

        // --- bias partials: thread (quad, j) covers 32 dims ---
        {
            int j = tid & 63, quad = tid >> 6;
            float pb[NH];
            #pragma unroll
            for (int n=0;n<NH;n++) pb[n] = 0.f;
            const float* er = e_s + j*ROWF + quad*32;
            const float* wb = Wpb_s + quad*32*NH;
            #pragma unroll
            for (int dd = 0; dd < 32; dd++) {
                float ev = er[dd];
                #pragma unroll
                for (int n=0;n<NH;n++) pb[n] += ev * wb[dd*NH + n];
            }
            float* po = part_s + (quad*64 + j)*9;
            #pragma unroll
            for (int n=0;n<NH;n++) po[n] = pb[n];
        }
        __syncthreads();

        // --- full logits (2 heads per thread) ---
        {
            int j = tid & 63, nb = tid >> 6;
            #pragma unroll
            for (int h = 0; h < 2; h++) {
                int n = nb + h*4;
                float bias = part_s[(0*64+j)*9+n] + part_s[(1*64+j)*9+n]
                           + part_s[(2*64+j)*9+n] + part_s[(3*64+j)*9+n];
                const float4* kr = (const float4*)(g_ks + ((b*NH+n)*LSEQ + j0 + j)*DS);
                float dot = 0.f;
                #pragma unroll
                for (int q4 = 0; q4 < 4; q4++) {
                    float4 kv = kr[q4];
                    const float* qq = qs_s + n*DS + q4*4;
                    dot += qq[0]*kv.x + qq[1]*kv.y + qq[2]*kv.z + qq[3]*kv.w;
                }
                const float4* kp = (const float4*)(g_kp + ((b*NH+n)*LSEQ + j0 + j)*12);
                float sq = 0.f;
                #pragma unroll
                for (int q4 = 0; q4 < 3; q4++) {
                    float4 kv = kp[q4];
                    const float* qq = qp_s + n*12 + q4*4;
                    float d0 = qq[0]-kv.x, d1 = qq[1]-kv.y, d2 = qq[2]-kv.z, d3 = qq[3]-kv.w;
                    sq += d0*d0 + d1*d1 + d2*d2 + d3*d3;
                }
                logit_s[n*66 + j] = SCALE_TOTAL*(SCALE_SCALAR*dot + bias
                                    - 0.5f*SCALE_POINT*gamma_s[n]*sq);
            }
        }
        __syncthreads();

        // --- per-head online softmax + out_s / out_p (warp = head) ---
        {
            int n = warp;
            float l0 = logit_s[n*66 + lane], l1 = logit_s[n*66 + lane + 32];
            float mt = fmaxf(l0, l1);
            #pragma unroll
            for (int o = 16; o > 0; o >>= 1)
                mt = fmaxf(mt, __shfl_xor_sync(0xffffffffu, mt, o));
            float m_new = fmaxf(m_run, mt);
            float alpha = __expf(m_run - m_new);
            float p0 = __expf(l0 - m_new), p1 = __expf(l1 - m_new);
            prob_s[n*66 + lane] = p0;
            prob_s[n*66 + lane + 32] = p1;
            float s = p0 + p1;
            #pragma unroll
            for (int o = 16; o > 0; o >>= 1)
                s += __shfl_xor_sync(0xffffffffu, s, o);
            denom = denom*alpha + s;
            m_run = m_new;
            if (lane == 0) alpha_s[n] = alpha;
            __syncwarp();
            acc_sp *= alpha;
            if (lane < 28) {
                const float* vb; int st;
                if (lane < 16) { vb = g_vs + ((b*NH+n)*LSEQ + j0)*DS + lane; st = DS; }
                else           { vb = g_vp + ((b*NH+n)*LSEQ + j0)*12 + (lane-16); st = 12; }
                float a = 0.f;
                #pragma unroll 8
                for (int j = 0; j < TJ; j++) a += prob_s[n*66+j] * vb[j*st];
                acc_sp += a;
            }
        }
        __syncthreads();   // alphas + probs visible to all warps

        // --- out_pair partial accumulate: warp owns a j-slice, lane owns 4 dims
        {
            #pragma unroll
            for (int n=0;n<NH;n++) {
                float a = alpha_s[n];
                #pragma unroll
                for (int c=0;c<4;c++) acc_e[n][c] *= a;
            }
            int jb = warp*8;
            #pragma unroll
            for (int jj = 0; jj < 8; jj++) {
                int j = jb + jj;
                float4 ev = *(const float4*)(e_s + j*ROWF + lane*4);
                #pragma unroll
                for (int n=0;n<NH;n++) {
                    float p = prob_s[n*66 + j];
                    acc_e[n][0] += p*ev.x; acc_e[n][1] += p*ev.y;
                    acc_e[n][2] += p*ev.z; acc_e[n][3] += p*ev.w;
                }
            }
        }
        __syncthreads();   // before next tile overwrites e_s
    }

    // ------------- finalize -------------
    float inv_d = 1.f / denom;
    if (lane == 0) denom_s[warp] = denom;
    if (lane < 16)      os_s[warp*16 + lane]        = acc_sp * inv_d;
    else if (lane < 28) op_s[warp*12 + (lane-16)]   = acc_sp * inv_d;
    __syncthreads();

    // cross-warp reduce of out_pair partials via e_s (reused)
    #pragma unroll
    for (int n=0;n<NH;n++)
        *(float4*)(e_s + (warp*NH + n)*128 + lane*4) =
            make_float4(acc_e[n][0], acc_e[n][1], acc_e[n][2], acc_e[n][3]);
    __syncthreads();

    float* feat = g_feat + (size_t)row * NFEAT;
    #pragma unroll
    for (int k = 0; k < 4; k++) {
        int o = tid + k*256;
        int n = o >> 7, d = o & 127;
        float s = 0.f;
        #pragma unroll
        for (int w = 0; w < 8; w++) s += e_s[(w*NH+n)*128 + d];
        feat[128 + n*128 + d] = s / denom_s[n];
    }
    if (tid < 128) feat[tid] = os_s[tid];
    if (tid < 32) {
        int n = tid >> 2, p = tid & 3;
        const float* rr = R + row*9;
        const float* tt = T + row*3;
        float o0 = op_s[n*12+p*3+0] - tt[0];
        float o1 = op_s[n*12+p*3+1] - tt[1];
        float o2 = op_s[n*12+p*3+2] - tt[2];
        float nsq = 0.f;
        #pragma unroll
        for (int c = 0; c < 3; c++) {
            float lc = o0*rr[c*3+0] + o1*rr[c*3+1] + o2*rr[c*3+2];
            feat[1152 + n*12 + p*3 + c] = lc;
            nsq += lc*lc;
        }
        feat[1248 + n*4 + p] = sqrtf(nsq);
    }
}

// ---------------- kernel 4: output GEMM  out = feat @ Wout + bout --------
__global__ void __launch_bounds__(256) out_gemm(
    const float* __restrict__ Wout, const float* __restrict__ bout,
    float* __restrict__ out)
{
    __shared__ float As[8*65];
    __shared__ float Bs[8*64];
    int tid = threadIdx.x;
    int tx = tid & 15, ty = tid >> 4;
    int row0 = blockIdx.y * 64;
    int col0 = blockIdx.x * 64;
    float acc[4][4];
    #pragma unroll
    for (int i=0;i<4;i++)
        #pragma unroll
        for (int j=0;j<4;j++) acc[i][j]=0.f;

    for (int k0 = 0; k0 < NFEAT; k0 += 8) {
        #pragma unroll
        for (int s = 0; s < 2; s++) {
            int li = tid + s*256;
            int r = li >> 3, c = li & 7;
            As[c*65 + r] = g_feat[(size_t)(row0 + r)*NFEAT + k0 + c];
        }
        #pragma unroll
        for (int s = 0; s < 2; s++) {
            int li = tid + s*256;
            int kr = li >> 6, c = li & 63;
            Bs[kr*64 + c] = Wout[(size_t)(k0+kr)*DRES + col0 + c];
        }
        __syncthreads();
        #pragma unroll
        for (int kk = 0; kk < 8; kk++) {
            float a[4], bb[4];
            #pragma unroll
            for (int i=0;i<4;i++) a[i]  = As[kk*65 + ty*4 + i];
            #pragma unroll
            for (int j=0;j<4;j++) bb[j] = Bs[kk*64 + tx*4 + j];
            #pragma unroll
            for (int i=0;i<4;i++)
                #pragma unroll
                for (int j=0;j<4;j++) acc[i][j] += a[i]*bb[j];
        }
        __syncthreads();
    }
    #pragma unroll
    for (int i=0;i<4;i++) {
        int row = row0 + ty*4 + i;
        #pragma unroll
        for (int j=0;j<4;j++) {
            int col = col0 + tx*4 + j;
            out[(size_t)row*DRES + col] = acc[i][j] + bout[col];
        }
    }
}

// ---------------- launch ----------------
extern "C" void kernel_launch(void* const* d_in, const int* in_sizes, int n_in,
                              void* d_out, int out_size)
{
    const float* x     = (const float*)d_in[0];
    const float* e     = (const float*)d_in[1];
    const float* r     = (const float*)d_in[2];
    const float* t     = (const float*)d_in[3];
    const float* Wqs   = (const float*)d_in[4];
    const float* Wks   = (const float*)d_in[5];
    const float* Wvs   = (const float*)d_in[6];
    const float* Wpb   = (const float*)d_in[7];
    const float* Wqp   = (const float*)d_in[8];
    const float* Wkp   = (const float*)d_in[9];
    const float* Wvp   = (const float*)d_in[10];
    const float* gamma = (const float*)d_in[11];
    const float* Wout  = (const float*)d_in[12];
    const float* bout  = (const float*)d_in[13];
    float* out = (float*)d_out;

    proj_gemm<<<dim3(11, 16), 256>>>(x, Wqs, Wks, Wvs, Wqp, Wkp, Wvp);
    point_transform<<<NROW, 96>>>(r, t);

    cudaFuncSetAttribute(ipa_attn, cudaFuncAttributeMaxDynamicSharedMemorySize,
                         SMEM_FLOATS * (int)sizeof(float));
    ipa_attn<<<NROW, 256, SMEM_FLOATS * sizeof(float)>>>(e, r, t, Wpb, gamma);

    out_gemm<<<dim3(6, 16), 256>>>(Wout, bout, out);
}

// round 6
// speedup vs baseline: 1.3396x; 1.3396x over previous
#include <cuda_runtime.h>
#include <math.h>

#define NH      8
#define LSEQ    512
#define DRES    384
#define DPAIR   128
#define DS      16
#define TJ      64
#define ROWF    132
#define NROW    1024
#define NFEAT   1280
#define NPROJ   672

#define SCALE_SCALAR 0.25f
#define SCALE_POINT  0.2357022603955158f   /* 18^-0.5 */
#define SCALE_TOTAL  0.5773502691896258f   /* 3^-0.5  */

// ---------------- scratch (device globals; no allocation) ----------------
__device__ float g_qs[2*NH*LSEQ*DS];
__device__ float g_ks[2*NH*LSEQ*DS];
__device__ float g_vs[2*NH*LSEQ*DS];
__device__ float g_qp[2*NH*LSEQ*12];
__device__ float g_kp[2*NH*LSEQ*12];
__device__ float g_vp[2*NH*LSEQ*12];
__device__ float g_praw[NROW*288];
__device__ float g_feat[(size_t)NROW*NFEAT];

// ===================== fp32 GEMM core: 32x32 tile, BK=16, 64 thr =========
// As stored transposed [k][m] pitch 36; Bs [k][n] pitch 32. Double-buffered.

// ---------------- kernel 1: projection GEMM  C[1024][672] = X @ [W...] ---
__global__ void __launch_bounds__(64) proj_gemm(
    const float* __restrict__ X,
    const float* __restrict__ Wqs, const float* __restrict__ Wks,
    const float* __restrict__ Wvs, const float* __restrict__ Wqp,
    const float* __restrict__ Wkp, const float* __restrict__ Wvp)
{
    __shared__ float As[2][16*36];
    __shared__ float Bs[2][16*32];
    const int tid = threadIdx.x;
    const int tx = tid & 7, ty = tid >> 3;
    const int row0 = blockIdx.y * 32;
    const int col0 = blockIdx.x * 32;

    // resolve weight segment for this 32-col tile (boundaries all mult of 32)
    const float* Wseg; int segw, cl0;
    if (col0 < 384) {
        int sg = col0 >> 7;
        Wseg = (sg==0) ? Wqs : ((sg==1) ? Wks : Wvs);
        segw = 128; cl0 = col0 & 127;
    } else {
        int c2 = col0 - 384; int sg = c2 / 96;
        Wseg = (sg==0) ? Wqp : ((sg==1) ? Wkp : Wvp);
        segw = 96; cl0 = c2 - sg*96;
    }

    const int am = (tid >> 2) & 31 ? 0 : 0; (void)am;
    const int a_m0 = tid >> 2, a_k4 = tid & 3;      // +32 m per s
    const int b_k0 = tid >> 3, b_n4 = tid & 7;      // +8 k per s

    float acc[4][4];
    #pragma unroll
    for (int i=0;i<4;i++)
        #pragma unroll
        for (int j=0;j<4;j++) acc[i][j]=0.f;

    // prologue: load k-block 0 into buffer 0
    {
        #pragma unroll
        for (int s=0;s<2;s++) {
            int m = a_m0 + s*16;
            float4 v = *(const float4*)&X[(size_t)(row0+m)*DRES + a_k4*4];
            #pragma unroll
            for (int u=0;u<4;u++) As[0][(a_k4*4+u)*36 + m] = ((const float*)&v)[u];
        }
        #pragma unroll
        for (int s=0;s<2;s++) {
            int k = b_k0 + s*8;
            *(float4*)&Bs[0][k*32 + b_n4*4] =
                *(const float4*)&Wseg[(size_t)k*segw + cl0 + b_n4*4];
        }
    }
    __syncthreads();

    const int KB = DRES/16;
    for (int kb = 0; kb < KB; kb++) {
        int cur = kb & 1;
        float4 va[2], vb[2];
        bool has = (kb+1 < KB);
        if (has) {
            int k0 = (kb+1)*16;
            #pragma unroll
            for (int s=0;s<2;s++) {
                int m = a_m0 + s*16;
                va[s] = *(const float4*)&X[(size_t)(row0+m)*DRES + k0 + a_k4*4];
                int k = b_k0 + s*8;
                vb[s] = *(const float4*)&Wseg[(size_t)(k0+k)*segw + cl0 + b_n4*4];
            }
        }
        #pragma unroll
        for (int kk = 0; kk < 16; kk++) {
            float4 a = *(const float4*)&As[cur][kk*36 + ty*4];
            float4 b = *(const float4*)&Bs[cur][kk*32 + tx*4];
            const float* ap = (const float*)&a;
            const float* bp = (const float*)&b;
            #pragma unroll
            for (int i=0;i<4;i++)
                #pragma unroll
                for (int j=0;j<4;j++) acc[i][j] += ap[i]*bp[j];
        }
        if (has) {
            int nxt = cur ^ 1;
            #pragma unroll
            for (int s=0;s<2;s++) {
                int m = a_m0 + s*16;
                #pragma unroll
                for (int u=0;u<4;u++) As[nxt][(a_k4*4+u)*36 + m] = ((const float*)&va[s])[u];
                int k = b_k0 + s*8;
                *(float4*)&Bs[nxt][k*32 + b_n4*4] = vb[s];
            }
        }
        __syncthreads();
    }

    #pragma unroll
    for (int i=0;i<4;i++) {
        int row = row0 + ty*4 + i;
        int b = row >> 9, l = row & 511;
        #pragma unroll
        for (int j=0;j<4;j++) {
            int col = col0 + tx*4 + j;
            float v = acc[i][j];
            if (col < 384) {
                int sg = col >> 7;
                int n = (col & 127) >> 4, d = col & 15;
                float* dst = (sg==0) ? g_qs : ((sg==1) ? g_ks : g_vs);
                dst[(((b*NH)+n)*LSEQ + l)*DS + d] = v;
            } else {
                g_praw[row*288 + (col-384)] = v;
            }
        }
    }
}

// ---------------- kernel 2: euclid transform of projected points ---------
__global__ void point_transform(const float* __restrict__ R, const float* __restrict__ T)
{
    int row = blockIdx.x;
    int b = row >> 9, l = row & 511;
    int t = threadIdx.x;
    if (t >= 96) return;
    int tensor = t / 32, idx = t % 32;
    int n = idx >> 2, p = idx & 3;
    const float* xr = &g_praw[row*288 + tensor*96 + n*12 + p*3];
    const float* rr = &R[row*9];
    const float* tt = &T[row*3];
    float x0 = xr[0], x1 = xr[1], x2 = xr[2];
    float* dst = ((tensor==0) ? g_qp : ((tensor==1) ? g_kp : g_vp))
               + (((b*NH)+n)*LSEQ + l)*12 + p*3;
    #pragma unroll
    for (int c = 0; c < 3; c++)
        dst[c] = x0*rr[0*3+c] + x1*rr[1*3+c] + x2*rr[2*3+c] + tt[c];
}

// ---------------- kernel 3: fused IPA attention (single e read) ----------
#define OFF_E      0
#define OFF_WPB    8448
#define OFF_LOGIT  9472
#define OFF_PROB   10000
#define OFF_PART   10528
#define OFF_QS     12832
#define OFF_QP     12960
#define OFF_GAMMA  13056
#define OFF_ALPHA  13064
#define OFF_DENOM  13072
#define OFF_OS     13080
#define OFF_OP     13208
#define SMEM_FLOATS 13304

__global__ void __launch_bounds__(256) ipa_attn(
    const float* __restrict__ E, const float* __restrict__ R,
    const float* __restrict__ T, const float* __restrict__ Wpb,
    const float* __restrict__ gamma)
{
    extern __shared__ float sm[];
    float* e_s     = sm + OFF_E;
    float* Wpb_s   = sm + OFF_WPB;
    float* logit_s = sm + OFF_LOGIT;
    float* prob_s  = sm + OFF_PROB;
    float* part_s  = sm + OFF_PART;
    float* qs_s    = sm + OFF_QS;
    float* qp_s    = sm + OFF_QP;
    float* gamma_s = sm + OFF_GAMMA;
    float* alpha_s = sm + OFF_ALPHA;
    float* denom_s = sm + OFF_DENOM;
    float* os_s    = sm + OFF_OS;
    float* op_s    = sm + OFF_OP;

    int row = blockIdx.x;
    int b = row >> 9, i = row & 511;
    int tid = threadIdx.x;
    int warp = tid >> 5, lane = tid & 31;

    for (int k = tid; k < DPAIR*NH; k += 256) Wpb_s[k] = Wpb[k];
    if (tid < 128) { int n = tid >> 4, d = tid & 15;
        qs_s[tid] = g_qs[((b*NH+n)*LSEQ + i)*DS + d]; }
    if (tid < 96)  { int n = tid/12, pc = tid - n*12;
        qp_s[tid] = g_qp[((b*NH+n)*LSEQ + i)*12 + pc]; }
    if (tid < 8) gamma_s[tid] = gamma[tid];
    __syncthreads();

    float m_run = -1e30f, denom = 0.f, acc_sp = 0.f;
    float acc_e[NH][4];
    #pragma unroll
    for (int n=0;n<NH;n++)
        #pragma unroll
        for (int c=0;c<4;c++) acc_e[n][c] = 0.f;

    const float* Ebi = E + (size_t)row * LSEQ * DPAIR;

    for (int jt = 0; jt < LSEQ/TJ; jt++) {
        int j0 = jt * TJ;

        // --- load e tile (contiguous 32KB) -> padded smem rows ---
        const float4* esrc = (const float4*)(Ebi + (size_t)j0*DPAIR);
        #pragma unroll
        for (int it = 0; it < 8; it++) {
            int g = it*256 + tid;                  // float4 index
            float4 v = esrc[g];
            int j = g >> 5, d = (g & 31) * 4;
            *(float4*)(e_s + j*ROWF + d) = v;
        }
        __syncthreads();

        // --- bias partials: thread (quad, j) covers 32 dims (float4 LDS) ---
        {
            int j = tid & 63, quad = tid >> 6;
            float pb[NH];
            #pragma unroll
            for (int n=0;n<NH;n++) pb[n] = 0.f;
            const float4* er4 = (const float4*)(e_s + j*ROWF + quad*32);
            const float* wb0 = Wpb_s + quad*32*NH;
            #pragma unroll
            for (int d4 = 0; d4 < 8; d4++) {
                float4 ev = er4[d4];
                const float* wb = wb0 + d4*4*NH;
                #pragma unroll
                for (int n=0;n<NH;n++)
                    pb[n] += ev.x*wb[n] + ev.y*wb[NH+n]
                           + ev.z*wb[2*NH+n] + ev.w*wb[3*NH+n];
            }
            float* po = part_s + (quad*64 + j)*9;
            #pragma unroll
            for (int n=0;n<NH;n++) po[n] = pb[n];
        }
        __syncthreads();

        // --- full logits (2 heads per thread) ---
        {
            int j = tid & 63, nb = tid >> 6;
            #pragma unroll
            for (int h = 0; h < 2; h++) {
                int n = nb + h*4;
                float bias = part_s[(0*64+j)*9+n] + part_s[(1*64+j)*9+n]
                           + part_s[(2*64+j)*9+n] + part_s[(3*64+j)*9+n];
                const float4* kr = (const float4*)(g_ks + ((b*NH+n)*LSEQ + j0 + j)*DS);
                float dot = 0.f;
                #pragma unroll
                for (int q4 = 0; q4 < 4; q4++) {
                    float4 kv = kr[q4];
                    const float* qq = qs_s + n*DS + q4*4;
                    dot += qq[0]*kv.x + qq[1]*kv.y + qq[2]*kv.z + qq[3]*kv.w;
                }
                const float4* kp = (const float4*)(g_kp + ((b*NH+n)*LSEQ + j0 + j)*12);
                float sq = 0.f;
                #pragma unroll
                for (int q4 = 0; q4 < 3; q4++) {
                    float4 kv = kp[q4];
                    const float* qq = qp_s + n*12 + q4*4;
                    float d0 = qq[0]-kv.x, d1 = qq[1]-kv.y, d2 = qq[2]-kv.z, d3 = qq[3]-kv.w;
                    sq += d0*d0 + d1*d1 + d2*d2 + d3*d3;
                }
                logit_s[n*66 + j] = SCALE_TOTAL*(SCALE_SCALAR*dot + bias
                                    - 0.5f*SCALE_POINT*gamma_s[n]*sq);
            }
        }
        __syncthreads();

        // --- per-head online softmax + out_s / out_p (warp = head) ---
        {
            int n = warp;
            float l0 = logit_s[n*66 + lane], l1 = logit_s[n*66 + lane + 32];
            float mt = fmaxf(l0, l1);
            #pragma unroll
            for (int o = 16; o > 0; o >>= 1)
                mt = fmaxf(mt, __shfl_xor_sync(0xffffffffu, mt, o));
            float m_new = fmaxf(m_run, mt);
            float alpha = __expf(m_run - m_new);
            float p0 = __expf(l0 - m_new), p1 = __expf(l1 - m_new);
            prob_s[n*66 + lane] = p0;
            prob_s[n*66 + lane + 32] = p1;
            float s = p0 + p1;
            #pragma unroll
            for (int o = 16; o > 0; o >>= 1)
                s += __shfl_xor_sync(0xffffffffu, s, o);
            denom = denom*alpha + s;
            m_run = m_new;
            if (lane == 0) alpha_s[n] = alpha;
            __syncwarp();
            acc_sp *= alpha;
            if (lane < 28) {
                const float* vb; int st;
                if (lane < 16) { vb = g_vs + ((b*NH+n)*LSEQ + j0)*DS + lane; st = DS; }
                else           { vb = g_vp + ((b*NH+n)*LSEQ + j0)*12 + (lane-16); st = 12; }
                float a = 0.f;
                #pragma unroll 8
                for (int j = 0; j < TJ; j++) a += prob_s[n*66+j] * vb[j*st];
                acc_sp += a;
            }
        }
        __syncthreads();   // alphas + probs visible to all warps

        // --- out_pair partial accumulate: warp owns a j-slice, lane owns 4 dims
        {
            #pragma unroll
            for (int n=0;n<NH;n++) {
                float a = alpha_s[n];
                #pragma unroll
                for (int c=0;c<4;c++) acc_e[n][c] *= a;
            }
            int jb = warp*8;
            #pragma unroll
            for (int jj = 0; jj < 8; jj++) {
                int j = jb + jj;
                float4 ev = *(const float4*)(e_s + j*ROWF + lane*4);
                #pragma unroll
                for (int n=0;n<NH;n++) {
                    float p = prob_s[n*66 + j];
                    acc_e[n][0] += p*ev.x; acc_e[n][1] += p*ev.y;
                    acc_e[n][2] += p*ev.z; acc_e[n][3] += p*ev.w;
                }
            }
        }
        __syncthreads();   // before next tile overwrites e_s
    }

    // ------------- finalize -------------
    float inv_d = 1.f / denom;
    if (lane == 0) denom_s[warp] = denom;
    if (lane < 16)      os_s[warp*16 + lane]        = acc_sp * inv_d;
    else if (lane < 28) op_s[warp*12 + (lane-16)]   = acc_sp * inv_d;
    __syncthreads();

    // cross-warp reduce of out_pair partials via e_s (reused)
    #pragma unroll
    for (int n=0;n<NH;n++)
        *(float4*)(e_s + (warp*NH + n)*128 + lane*4) =
            make_float4(acc_e[n][0], acc_e[n][1], acc_e[n][2], acc_e[n][3]);
    __syncthreads();

    float* feat = g_feat + (size_t)row * NFEAT;
    #pragma unroll
    for (int k = 0; k < 4; k++) {
        int o = tid + k*256;
        int n = o >> 7, d = o & 127;
        float s = 0.f;
        #pragma unroll
        for (int w = 0; w < 8; w++) s += e_s[(w*NH+n)*128 + d];
        feat[128 + n*128 + d] = s / denom_s[n];
    }
    if (tid < 128) feat[tid] = os_s[tid];
    if (tid < 32) {
        int n = tid >> 2, p = tid & 3;
        const float* rr = R + row*9;
        const float* tt = T + row*3;
        float o0 = op_s[n*12+p*3+0] - tt[0];
        float o1 = op_s[n*12+p*3+1] - tt[1];
        float o2 = op_s[n*12+p*3+2] - tt[2];
        float nsq = 0.f;
        #pragma unroll
        for (int c = 0; c < 3; c++) {
            float lc = o0*rr[c*3+0] + o1*rr[c*3+1] + o2*rr[c*3+2];
            feat[1152 + n*12 + p*3 + c] = lc;
            nsq += lc*lc;
        }
        feat[1248 + n*4 + p] = sqrtf(nsq);
    }
}

// ---------------- kernel 4: output GEMM  out = feat @ Wout + bout --------
__global__ void __launch_bounds__(64) out_gemm(
    const float* __restrict__ Wout, const float* __restrict__ bout,
    float* __restrict__ out)
{
    __shared__ float As[2][16*36];
    __shared__ float Bs[2][16*32];
    const int tid = threadIdx.x;
    const int tx = tid & 7, ty = tid >> 3;
    const int row0 = blockIdx.y * 32;
    const int col0 = blockIdx.x * 32;

    const int a_m0 = tid >> 2, a_k4 = tid & 3;
    const int b_k0 = tid >> 3, b_n4 = tid & 7;

    float acc[4][4];
    #pragma unroll
    for (int i=0;i<4;i++)
        #pragma unroll
        for (int j=0;j<4;j++) acc[i][j]=0.f;

    {
        #pragma unroll
        for (int s=0;s<2;s++) {
            int m = a_m0 + s*16;
            float4 v = *(const float4*)&g_feat[(size_t)(row0+m)*NFEAT + a_k4*4];
            #pragma unroll
            for (int u=0;u<4;u++) As[0][(a_k4*4+u)*36 + m] = ((const float*)&v)[u];
            int k = b_k0 + s*8;
            *(float4*)&Bs[0][k*32 + b_n4*4] =
                *(const float4*)&Wout[(size_t)k*DRES + col0 + b_n4*4];
        }
    }
    __syncthreads();

    const int KB = NFEAT/16;
    for (int kb = 0; kb < KB; kb++) {
        int cur = kb & 1;
        float4 va[2], vb[2];
        bool has = (kb+1 < KB);
        if (has) {
            int k0 = (kb+1)*16;
            #pragma unroll
            for (int s=0;s<2;s++) {
                int m = a_m0 + s*16;
                va[s] = *(const float4*)&g_feat[(size_t)(row0+m)*NFEAT + k0 + a_k4*4];
                int k = b_k0 + s*8;
                vb[s] = *(const float4*)&Wout[(size_t)(k0+k)*DRES + col0 + b_n4*4];
            }
        }
        #pragma unroll
        for (int kk = 0; kk < 16; kk++) {
            float4 a = *(const float4*)&As[cur][kk*36 + ty*4];
            float4 b = *(const float4*)&Bs[cur][kk*32 + tx*4];
            const float* ap = (const float*)&a;
            const float* bp = (const float*)&b;
            #pragma unroll
            for (int i=0;i<4;i++)
                #pragma unroll
                for (int j=0;j<4;j++) acc[i][j] += ap[i]*bp[j];
        }
        if (has) {
            int nxt = cur ^ 1;
            #pragma unroll
            for (int s=0;s<2;s++) {
                int m = a_m0 + s*16;
                #pragma unroll
                for (int u=0;u<4;u++) As[nxt][(a_k4*4+u)*36 + m] = ((const float*)&va[s])[u];
                int k = b_k0 + s*8;
                *(float4*)&Bs[nxt][k*32 + b_n4*4] = vb[s];
            }
        }
        __syncthreads();
    }

    float4 bv = *(const float4*)&bout[col0 + tx*4];
    #pragma unroll
    for (int i=0;i<4;i++) {
        int row = row0 + ty*4 + i;
        float4 o;
        o.x = acc[i][0] + bv.x;
        o.y = acc[i][1] + bv.y;
        o.z = acc[i][2] + bv.z;
        o.w = acc[i][3] + bv.w;
        *(float4*)&out[(size_t)row*DRES + col0 + tx*4] = o;
    }
}

// ---------------- launch ----------------
extern "C" void kernel_launch(void* const* d_in, const int* in_sizes, int n_in,
                              void* d_out, int out_size)
{
    const float* x     = (const float*)d_in[0];
    const float* e     = (const float*)d_in[1];
    const float* r     = (const float*)d_in[2];
    const float* t     = (const float*)d_in[3];
    const float* Wqs   = (const float*)d_in[4];
    const float* Wks   = (const float*)d_in[5];
    const float* Wvs   = (const float*)d_in[6];
    const float* Wpb   = (const float*)d_in[7];
    const float* Wqp   = (const float*)d_in[8];
    const float* Wkp   = (const float*)d_in[9];
    const float* Wvp   = (const float*)d_in[10];
    const float* gamma = (const float*)d_in[11];
    const float* Wout  = (const float*)d_in[12];
    const float* bout  = (const float*)d_in[13];
    float* out = (float*)d_out;

    proj_gemm<<<dim3(21, 32), 64>>>(x, Wqs, Wks, Wvs, Wqp, Wkp, Wvp);
    point_transform<<<NROW, 96>>>(r, t);

    cudaFuncSetAttribute(ipa_attn, cudaFuncAttributeMaxDynamicSharedMemorySize,
                         SMEM_FLOATS * (int)sizeof(float));
    ipa_attn<<<NROW, 256, SMEM_FLOATS * sizeof(float)>>>(e, r, t, Wpb, gamma);

    out_gemm<<<dim3(12, 32), 64>>>(Wout, bout, out);
}